// round 1
// baseline (speedup 1.0000x reference)
#include <cuda_runtime.h>
#include <math.h>

// ---------------- problem constants ----------------
#define BSZ   2
#define LQ    17821
#define CDIM  256
#define MTOK  (BSZ*LQ)          // 35642
#define DFFN  1024
#define NHEAD 8
#define NLVL  4
#define NPTS  4
#define DHEAD 32

// level shapes (H,W) and start indices, baked in (static per problem)
__device__ __constant__ int c_H[4]  = {100, 50, 25, 13};
__device__ __constant__ int c_W[4]  = {134, 67, 34, 17};
__device__ __constant__ int c_st[4] = {0, 13400, 16750, 17600};

// ---------------- scratch buffers (no allocs allowed) ----------------
__device__ float d_normed[(size_t)MTOK*CDIM];
__device__ float d_q     [(size_t)MTOK*CDIM];
__device__ float d_value [(size_t)MTOK*CDIM];
__device__ float d_off   [(size_t)MTOK*CDIM];
__device__ float d_awl   [(size_t)MTOK*(NHEAD*NLVL*NPTS)];
__device__ float d_attn  [(size_t)MTOK*CDIM];
__device__ float d_x     [(size_t)MTOK*CDIM];
__device__ float d_n2    [(size_t)MTOK*CDIM];
__device__ float d_h     [(size_t)MTOK*DFFN];

// ---------------- RMSNorm (+ optional addend second output) ----------------
// one warp per row of 256 floats; 8 rows per 256-thread block
__global__ void __launch_bounds__(256) rmsnorm_kernel(
    const float* __restrict__ x, const float* __restrict__ w,
    float* __restrict__ out, const float* __restrict__ addend,
    float* __restrict__ out2)
{
    int row  = blockIdx.x * 8 + (threadIdx.x >> 5);
    if (row >= MTOK) return;
    int lane = threadIdx.x & 31;
    const float4* xr = (const float4*)(x + (size_t)row * CDIM);
    float4 v0 = xr[lane];
    float4 v1 = xr[lane + 32];
    float ss = v0.x*v0.x + v0.y*v0.y + v0.z*v0.z + v0.w*v0.w
             + v1.x*v1.x + v1.y*v1.y + v1.z*v1.z + v1.w*v1.w;
    #pragma unroll
    for (int o = 16; o > 0; o >>= 1) ss += __shfl_xor_sync(0xffffffffu, ss, o);
    float s = rsqrtf(ss * (1.0f / CDIM) + 1e-6f);

    const float4* w4 = (const float4*)w;
    float4 g0 = w4[lane], g1 = w4[lane + 32];
    float4 n0, n1;
    n0.x = v0.x*s*g0.x; n0.y = v0.y*s*g0.y; n0.z = v0.z*s*g0.z; n0.w = v0.w*s*g0.w;
    n1.x = v1.x*s*g1.x; n1.y = v1.y*s*g1.y; n1.z = v1.z*s*g1.z; n1.w = v1.w*s*g1.w;
    float4* o4 = (float4*)(out + (size_t)row * CDIM);
    o4[lane] = n0; o4[lane + 32] = n1;
    if (out2) {
        const float4* a4 = (const float4*)(addend + (size_t)row * CDIM);
        float4 p0 = a4[lane], p1 = a4[lane + 32];
        float4 q0, q1;
        q0.x = n0.x + p0.x; q0.y = n0.y + p0.y; q0.z = n0.z + p0.z; q0.w = n0.w + p0.w;
        q1.x = n1.x + p1.x; q1.y = n1.y + p1.y; q1.z = n1.z + p1.z; q1.w = n1.w + p1.w;
        float4* q4 = (float4*)(out2 + (size_t)row * CDIM);
        q4[lane] = q0; q4[lane + 32] = q1;
    }
}

// ---------------- generic SGEMM:  out[m,n] = sum_k A[m,k] * W[n,k] + bias[n] ----------------
// optional epilogue: out = residual + gain[n] * (acc + bias[n])
#define BM 64
#define BN 64
#define BK 16

__global__ void __launch_bounds__(256) gemm_kernel(
    const float* __restrict__ A, const float* __restrict__ W,
    const float* __restrict__ bias, float* __restrict__ out,
    int M, int N, int K,
    const float* __restrict__ residual, const float* __restrict__ gain)
{
    __shared__ float As[BK][BM + 4];
    __shared__ float Ws[BK][BN + 4];
    int tid = threadIdx.x;
    int lr  = tid >> 2;            // 0..63
    int lc  = (tid & 3) << 2;      // 0,4,8,12
    int m0  = blockIdx.y * BM;
    int n0  = blockIdx.x * BN;
    int tx  = tid & 15, ty = tid >> 4;
    float acc[4][4] = {};

    for (int k0 = 0; k0 < K; k0 += BK) {
        float4 a4 = make_float4(0.f, 0.f, 0.f, 0.f);
        int gm = m0 + lr;
        if (gm < M) a4 = *(const float4*)(A + (size_t)gm * K + k0 + lc);
        As[lc+0][lr] = a4.x; As[lc+1][lr] = a4.y; As[lc+2][lr] = a4.z; As[lc+3][lr] = a4.w;
        float4 w4 = *(const float4*)(W + (size_t)(n0 + lr) * K + k0 + lc);
        Ws[lc+0][lr] = w4.x; Ws[lc+1][lr] = w4.y; Ws[lc+2][lr] = w4.z; Ws[lc+3][lr] = w4.w;
        __syncthreads();
        #pragma unroll
        for (int k = 0; k < BK; k++) {
            float4 av = *(const float4*)&As[k][ty * 4];
            float4 wv = *(const float4*)&Ws[k][tx * 4];
            acc[0][0] += av.x*wv.x; acc[0][1] += av.x*wv.y; acc[0][2] += av.x*wv.z; acc[0][3] += av.x*wv.w;
            acc[1][0] += av.y*wv.x; acc[1][1] += av.y*wv.y; acc[1][2] += av.y*wv.z; acc[1][3] += av.y*wv.w;
            acc[2][0] += av.z*wv.x; acc[2][1] += av.z*wv.y; acc[2][2] += av.z*wv.z; acc[2][3] += av.z*wv.w;
            acc[3][0] += av.w*wv.x; acc[3][1] += av.w*wv.y; acc[3][2] += av.w*wv.z; acc[3][3] += av.w*wv.w;
        }
        __syncthreads();
    }

    int nbase = n0 + tx * 4;
    float4 bs = *(const float4*)(bias + nbase);
    float4 gv = make_float4(0.f,0.f,0.f,0.f);
    if (gain) gv = *(const float4*)(gain + nbase);
    #pragma unroll
    for (int i = 0; i < 4; i++) {
        int m = m0 + ty * 4 + i;
        if (m >= M) continue;
        float4 v;
        v.x = acc[i][0] + bs.x; v.y = acc[i][1] + bs.y;
        v.z = acc[i][2] + bs.z; v.w = acc[i][3] + bs.w;
        if (residual) {
            float4 r = *(const float4*)(residual + (size_t)m * N + nbase);
            v.x = r.x + gv.x * v.x; v.y = r.y + gv.y * v.y;
            v.z = r.z + gv.z * v.z; v.w = r.w + gv.w * v.w;
        }
        *(float4*)(out + (size_t)m * N + nbase) = v;
    }
}

// ---------------- fused FFN-up: h = silu(A@W1^T+b1) * (A@W2^T+b2) ----------------
__global__ void __launch_bounds__(256) dualgemm_kernel(
    const float* __restrict__ A,
    const float* __restrict__ W1, const float* __restrict__ b1,
    const float* __restrict__ W2, const float* __restrict__ b2,
    float* __restrict__ out, int M, int N, int K)
{
    __shared__ float As [BK][BM + 4];
    __shared__ float W1s[BK][BN + 4];
    __shared__ float W2s[BK][BN + 4];
    int tid = threadIdx.x;
    int lr  = tid >> 2;
    int lc  = (tid & 3) << 2;
    int m0  = blockIdx.y * BM;
    int n0  = blockIdx.x * BN;
    int tx  = tid & 15, ty = tid >> 4;
    float acc1[4][4] = {}, acc2[4][4] = {};

    for (int k0 = 0; k0 < K; k0 += BK) {
        float4 a4 = make_float4(0.f, 0.f, 0.f, 0.f);
        int gm = m0 + lr;
        if (gm < M) a4 = *(const float4*)(A + (size_t)gm * K + k0 + lc);
        As[lc+0][lr] = a4.x; As[lc+1][lr] = a4.y; As[lc+2][lr] = a4.z; As[lc+3][lr] = a4.w;
        float4 w4 = *(const float4*)(W1 + (size_t)(n0 + lr) * K + k0 + lc);
        W1s[lc+0][lr] = w4.x; W1s[lc+1][lr] = w4.y; W1s[lc+2][lr] = w4.z; W1s[lc+3][lr] = w4.w;
        float4 u4 = *(const float4*)(W2 + (size_t)(n0 + lr) * K + k0 + lc);
        W2s[lc+0][lr] = u4.x; W2s[lc+1][lr] = u4.y; W2s[lc+2][lr] = u4.z; W2s[lc+3][lr] = u4.w;
        __syncthreads();
        #pragma unroll
        for (int k = 0; k < BK; k++) {
            float4 av = *(const float4*)&As[k][ty * 4];
            float4 w1 = *(const float4*)&W1s[k][tx * 4];
            float4 w2 = *(const float4*)&W2s[k][tx * 4];
            acc1[0][0] += av.x*w1.x; acc1[0][1] += av.x*w1.y; acc1[0][2] += av.x*w1.z; acc1[0][3] += av.x*w1.w;
            acc1[1][0] += av.y*w1.x; acc1[1][1] += av.y*w1.y; acc1[1][2] += av.y*w1.z; acc1[1][3] += av.y*w1.w;
            acc1[2][0] += av.z*w1.x; acc1[2][1] += av.z*w1.y; acc1[2][2] += av.z*w1.z; acc1[2][3] += av.z*w1.w;
            acc1[3][0] += av.w*w1.x; acc1[3][1] += av.w*w1.y; acc1[3][2] += av.w*w1.z; acc1[3][3] += av.w*w1.w;
            acc2[0][0] += av.x*w2.x; acc2[0][1] += av.x*w2.y; acc2[0][2] += av.x*w2.z; acc2[0][3] += av.x*w2.w;
            acc2[1][0] += av.y*w2.x; acc2[1][1] += av.y*w2.y; acc2[1][2] += av.y*w2.z; acc2[1][3] += av.y*w2.w;
            acc2[2][0] += av.z*w2.x; acc2[2][1] += av.z*w2.y; acc2[2][2] += av.z*w2.z; acc2[2][3] += av.z*w2.w;
            acc2[3][0] += av.w*w2.x; acc2[3][1] += av.w*w2.y; acc2[3][2] += av.w*w2.z; acc2[3][3] += av.w*w2.w;
        }
        __syncthreads();
    }

    int nbase = n0 + tx * 4;
    float4 bb1 = *(const float4*)(b1 + nbase);
    float4 bb2 = *(const float4*)(b2 + nbase);
    #pragma unroll
    for (int i = 0; i < 4; i++) {
        int m = m0 + ty * 4 + i;
        if (m >= M) continue;
        float z[4], g[4];
        z[0] = acc1[i][0] + bb1.x; z[1] = acc1[i][1] + bb1.y;
        z[2] = acc1[i][2] + bb1.z; z[3] = acc1[i][3] + bb1.w;
        g[0] = acc2[i][0] + bb2.x; g[1] = acc2[i][1] + bb2.y;
        g[2] = acc2[i][2] + bb2.z; g[3] = acc2[i][3] + bb2.w;
        float4 v;
        v.x = (z[0] / (1.0f + __expf(-z[0]))) * g[0];
        v.y = (z[1] / (1.0f + __expf(-z[1]))) * g[1];
        v.z = (z[2] / (1.0f + __expf(-z[2]))) * g[2];
        v.w = (z[3] / (1.0f + __expf(-z[3]))) * g[3];
        *(float4*)(out + (size_t)m * N + nbase) = v;
    }
}

// ---------------- deformable-attention sampling ----------------
// one block per token, one warp per head, one lane per channel (d=32)
__global__ void __launch_bounds__(256) msda_kernel(
    const float* __restrict__ ref,   // (bs, Lq, NL, 2)
    const float* __restrict__ value, // (bs, Lq, NH*32)
    const float* __restrict__ off,   // (bs*Lq, 256) = (NH, NL, NP, 2)
    const float* __restrict__ awl,   // (bs*Lq, 128) logits
    float* __restrict__ outp)        // (bs*Lq, 256)
{
    int token = blockIdx.x;
    int h    = threadIdx.x >> 5;
    int lane = threadIdx.x & 31;

    const float* aw = awl + (size_t)token * 128 + h * 16;
    const float* of = off + (size_t)token * 256 + h * 32;

    // softmax over 16 sampling weights (all lanes compute redundantly; broadcast loads)
    float wgt[16];
    float mx = -1e30f;
    #pragma unroll
    for (int s = 0; s < 16; s++) { wgt[s] = aw[s]; mx = fmaxf(mx, wgt[s]); }
    float sum = 0.f;
    #pragma unroll
    for (int s = 0; s < 16; s++) { wgt[s] = __expf(wgt[s] - mx); sum += wgt[s]; }
    float inv = 1.0f / sum;

    int b = token / LQ;
    const float* vb = value + (size_t)b * LQ * 256 + h * 32 + lane;

    float acc = 0.f;
    #pragma unroll
    for (int l = 0; l < NLVL; l++) {
        const int H  = c_H[l];
        const int W  = c_W[l];
        const int st = c_st[l];
        float rx = ref[(size_t)token * 8 + l * 2 + 0];
        float ry = ref[(size_t)token * 8 + l * 2 + 1];
        #pragma unroll
        for (int p = 0; p < NPTS; p++) {
            int s = l * 4 + p;
            float x = fmaf(rx, (float)W, of[s * 2 + 0] - 0.5f);
            float y = fmaf(ry, (float)H, of[s * 2 + 1] - 0.5f);
            float x0f = floorf(x), y0f = floorf(y);
            int   x0  = (int)x0f,  y0  = (int)y0f;
            float lx = x - x0f, ly = y - y0f;
            float ws  = wgt[s] * inv;
            float w00 = (1.f - lx) * (1.f - ly) * ws;
            float w01 = lx * (1.f - ly) * ws;
            float w10 = (1.f - lx) * ly * ws;
            float w11 = lx * ly * ws;
            bool x0v = (x0 >= 0)     && (x0 < W);
            bool x1v = (x0 + 1 >= 0) && (x0 + 1 < W);
            if (y0 >= 0 && y0 < H) {
                long long base = (long long)(st + y0 * W) * 256;
                if (x0v) acc += w00 * vb[base + (long long)x0 * 256];
                if (x1v) acc += w01 * vb[base + (long long)(x0 + 1) * 256];
            }
            int y1 = y0 + 1;
            if (y1 >= 0 && y1 < H) {
                long long base = (long long)(st + y1 * W) * 256;
                if (x0v) acc += w10 * vb[base + (long long)x0 * 256];
                if (x1v) acc += w11 * vb[base + (long long)(x0 + 1) * 256];
            }
        }
    }
    outp[(size_t)token * 256 + h * 32 + lane] = acc;
}

// ---------------- host launch ----------------
static float* symaddr(const void* sym) {
    void* p = nullptr;
    cudaGetSymbolAddress(&p, sym);
    return (float*)p;
}

extern "C" void kernel_launch(void* const* d_in, const int* in_sizes, int n_in,
                              void* d_out, int out_size) {
    (void)in_sizes; (void)n_in; (void)out_size;
    const float* query = (const float*)d_in[0];
    const float* qpos  = (const float*)d_in[1];
    const float* ref   = (const float*)d_in[2];
    // d_in[3] spatial_shapes, d_in[4] level_start_index: static, unused
    const float* nw1   = (const float*)d_in[5];
    const float* Wv    = (const float*)d_in[6];
    const float* bv    = (const float*)d_in[7];
    const float* Woff  = (const float*)d_in[8];
    const float* boff  = (const float*)d_in[9];
    const float* Waw   = (const float*)d_in[10];
    const float* baw   = (const float*)d_in[11];
    const float* Wo    = (const float*)d_in[12];
    const float* bo    = (const float*)d_in[13];
    const float* lsa   = (const float*)d_in[14];
    const float* nw2   = (const float*)d_in[15];
    const float* W1    = (const float*)d_in[16];
    const float* b1    = (const float*)d_in[17];
    const float* W2    = (const float*)d_in[18];
    const float* b2    = (const float*)d_in[19];
    const float* W3    = (const float*)d_in[20];
    const float* b3    = (const float*)d_in[21];
    const float* lsf   = (const float*)d_in[22];
    float* out = (float*)d_out;

    float* pn    = symaddr(d_normed);
    float* pq    = symaddr(d_q);
    float* pval  = symaddr(d_value);
    float* poff  = symaddr(d_off);
    float* pawl  = symaddr(d_awl);
    float* pattn = symaddr(d_attn);
    float* px    = symaddr(d_x);
    float* pn2   = symaddr(d_n2);
    float* ph    = symaddr(d_h);

    const int MB = (MTOK + BM - 1) / BM;   // 557

    // 1. norm + q = normed + query_pos
    rmsnorm_kernel<<<(MTOK + 7) / 8, 256>>>(query, nw1, pn, qpos, pq);
    // 2. value = normed @ Wv^T + bv
    gemm_kernel<<<dim3(CDIM / BN, MB), 256>>>(pn, Wv, bv, pval, MTOK, CDIM, CDIM, nullptr, nullptr);
    // 3. off = q @ Woff^T + boff
    gemm_kernel<<<dim3(CDIM / BN, MB), 256>>>(pq, Woff, boff, poff, MTOK, CDIM, CDIM, nullptr, nullptr);
    // 4. aw logits = q @ Waw^T + baw
    gemm_kernel<<<dim3(128 / BN, MB), 256>>>(pq, Waw, baw, pawl, MTOK, 128, CDIM, nullptr, nullptr);
    // 5. deformable sampling -> attn (pre-Wo)
    msda_kernel<<<MTOK, 256>>>(ref, pval, poff, pawl, pattn);
    // 6. x = query + ls_attn * (attn @ Wo^T + bo)
    gemm_kernel<<<dim3(CDIM / BN, MB), 256>>>(pattn, Wo, bo, px, MTOK, CDIM, CDIM, query, lsa);
    // 7. n2 = rmsnorm(x)
    rmsnorm_kernel<<<(MTOK + 7) / 8, 256>>>(px, nw2, pn2, nullptr, nullptr);
    // 8. h = silu(n2@W1^T+b1) * (n2@W2^T+b2)
    dualgemm_kernel<<<dim3(DFFN / BN, MB), 256>>>(pn2, W1, b1, W2, b2, ph, MTOK, DFFN, CDIM);
    // 9. out = x + ls_ffn * (h @ W3^T + b3)
    gemm_kernel<<<dim3(CDIM / BN, MB), 256>>>(ph, W3, b3, out, MTOK, CDIM, DFFN, px, lsf);
}

// round 3
// speedup vs baseline: 2.8684x; 2.8684x over previous
#include <cuda_runtime.h>
#include <cuda_bf16.h>
#include <cstdint>
#include <math.h>

// ---------------- problem constants ----------------
#define BSZ   2
#define LQ    17821
#define CDIM  256
#define MTOK  (BSZ*LQ)          // 35642
#define MPAD  35712             // 279 * 128
#define MT128 279
#define DFFN  1024
#define PAD   72                // smem row stride in halves (144B, conflict-free)

__device__ __constant__ int c_H[4]  = {100, 50, 25, 13};
__device__ __constant__ int c_W[4]  = {134, 67, 34, 17};
__device__ __constant__ int c_st[4] = {0, 13400, 16750, 17600};

// ---------------- scratch (no allocs allowed; zero-initialized .bss) ----------------
__device__ __nv_bfloat16 g_nb   [(size_t)MPAD*CDIM];
__device__ __nv_bfloat16 g_qb   [(size_t)MPAD*CDIM];
__device__ float         g_value[(size_t)MTOK*CDIM];
__device__ float         g_off  [(size_t)MTOK*CDIM];
__device__ float         g_awl  [(size_t)MTOK*128];
__device__ __nv_bfloat16 g_attnb[(size_t)MPAD*CDIM];
__device__ float         g_x    [(size_t)MTOK*CDIM];
__device__ __nv_bfloat16 g_n2b  [(size_t)MPAD*CDIM];
__device__ __nv_bfloat16 g_hb   [(size_t)MPAD*DFFN];
// converted weights, concatenated: Wv,Woff,Waw,Wo,W1,W2,W3
#define WOFF_WV   0
#define WOFF_WOFF 65536
#define WOFF_WAW  131072
#define WOFF_WO   163840
#define WOFF_W1   229376
#define WOFF_W2   491520
#define WOFF_W3   753664
__device__ __nv_bfloat16 g_wb[1015808];

// ================= helpers =================
__device__ __forceinline__ uint32_t smem_u32(const void* p) {
    uint32_t a;
    asm("{ .reg .u64 t; cvta.to.shared.u64 t, %1; cvt.u32.u64 %0, t; }" : "=r"(a) : "l"(p));
    return a;
}
__device__ __forceinline__ void ldsm4(uint32_t* r, uint32_t addr) {
    asm volatile("ldmatrix.sync.aligned.m8n8.x4.shared.b16 {%0,%1,%2,%3}, [%4];"
        : "=r"(r[0]), "=r"(r[1]), "=r"(r[2]), "=r"(r[3]) : "r"(addr));
}
__device__ __forceinline__ void mma_bf16(float* c, const uint32_t* a, const uint32_t* b) {
    asm volatile(
        "mma.sync.aligned.m16n8k16.row.col.f32.bf16.bf16.f32 "
        "{%0,%1,%2,%3}, {%4,%5,%6,%7}, {%8,%9}, {%0,%1,%2,%3};"
        : "+f"(c[0]), "+f"(c[1]), "+f"(c[2]), "+f"(c[3])
        : "r"(a[0]), "r"(a[1]), "r"(a[2]), "r"(a[3]), "r"(b[0]), "r"(b[1]));
}

// ---------------- weight fp32 -> bf16 convert (7 matrices, 1 launch) ----------------
struct WSrc { const float* s[7]; };
__device__ __constant__ int c_wsz [7] = {65536, 65536, 32768, 65536, 262144, 262144, 262144};
__device__ __constant__ int c_woff[7] = {WOFF_WV, WOFF_WOFF, WOFF_WAW, WOFF_WO, WOFF_W1, WOFF_W2, WOFF_W3};

__global__ void __launch_bounds__(256) wconv_kernel(WSrc w) {
    int seg = blockIdx.y;
    int i = (blockIdx.x * 256 + threadIdx.x) * 4;
    if (i >= c_wsz[seg]) return;
    float4 v = *(const float4*)(w.s[seg] + i);
    __nv_bfloat16* d = g_wb + c_woff[seg] + i;
    *(__nv_bfloat162*)(d)     = __floats2bfloat162_rn(v.x, v.y);
    *(__nv_bfloat162*)(d + 2) = __floats2bfloat162_rn(v.z, v.w);
}

// ---------------- RMSNorm -> bf16 (+ optional bf16 normed+addend) ----------------
__global__ void __launch_bounds__(256) rmsnorm_kernel(
    const float* __restrict__ x, const float* __restrict__ w,
    __nv_bfloat16* __restrict__ out, const float* __restrict__ addend,
    __nv_bfloat16* __restrict__ out2)
{
    int row  = blockIdx.x * 8 + (threadIdx.x >> 5);
    if (row >= MTOK) return;
    int lane = threadIdx.x & 31;
    const float4* xr = (const float4*)(x + (size_t)row * CDIM);
    float4 v0 = xr[lane];
    float4 v1 = xr[lane + 32];
    float ss = v0.x*v0.x + v0.y*v0.y + v0.z*v0.z + v0.w*v0.w
             + v1.x*v1.x + v1.y*v1.y + v1.z*v1.z + v1.w*v1.w;
    #pragma unroll
    for (int o = 16; o > 0; o >>= 1) ss += __shfl_xor_sync(0xffffffffu, ss, o);
    float s = rsqrtf(ss * (1.0f / CDIM) + 1e-6f);
    const float4* w4 = (const float4*)w;
    float4 g0 = w4[lane], g1 = w4[lane + 32];
    float n0x = v0.x*s*g0.x, n0y = v0.y*s*g0.y, n0z = v0.z*s*g0.z, n0w = v0.w*s*g0.w;
    float n1x = v1.x*s*g1.x, n1y = v1.y*s*g1.y, n1z = v1.z*s*g1.z, n1w = v1.w*s*g1.w;
    __nv_bfloat162* o2 = (__nv_bfloat162*)(out + (size_t)row * CDIM);
    o2[lane*2+0]  = __floats2bfloat162_rn(n0x, n0y);
    o2[lane*2+1]  = __floats2bfloat162_rn(n0z, n0w);
    o2[64+lane*2] = __floats2bfloat162_rn(n1x, n1y);
    o2[65+lane*2] = __floats2bfloat162_rn(n1z, n1w);
    if (out2) {
        const float4* a4 = (const float4*)(addend + (size_t)row * CDIM);
        float4 p0 = a4[lane], p1 = a4[lane + 32];
        __nv_bfloat162* q2 = (__nv_bfloat162*)(out2 + (size_t)row * CDIM);
        q2[lane*2+0]  = __floats2bfloat162_rn(n0x + p0.x, n0y + p0.y);
        q2[lane*2+1]  = __floats2bfloat162_rn(n0z + p0.z, n0w + p0.w);
        q2[64+lane*2] = __floats2bfloat162_rn(n1x + p1.x, n1y + p1.y);
        q2[65+lane*2] = __floats2bfloat162_rn(n1z + p1.z, n1w + p1.w);
    }
}

// ---------------- HMMA GEMM: out[m,n] = sum_k A[m,k]*B[n,k] + bias[n] ----------------
// optional: out = residual + gain[n]*(acc+bias). A is (MPAD,K) bf16 (padding rows read
// as zeros), B is (N,K) bf16. CTA tile 128x128, 8 warps (each 64x32), K chunk 64.
__global__ void __launch_bounds__(256) hmma_gemm_kernel(
    const __nv_bfloat16* __restrict__ A, const __nv_bfloat16* __restrict__ B,
    const float* __restrict__ bias, float* __restrict__ outp,
    int M, int N, int K,
    const float* __restrict__ residual, const float* __restrict__ gain)
{
    __shared__ __align__(16) uint16_t As[128 * PAD];
    __shared__ __align__(16) uint16_t Bs[128 * PAD];
    int tid = threadIdx.x, lane = tid & 31, wid = tid >> 5;
    int m0 = blockIdx.y * 128, n0 = blockIdx.x * 128;
    int warp_m = (wid & 1) * 64, warp_n = (wid >> 1) * 32;

    float acc[4][4][4] = {};

    int sub = lane >> 3, lrow = lane & 7;
    uint32_t a_base = smem_u32(As) + ((warp_m + (sub & 1) * 8 + lrow) * PAD + (sub >> 1) * 8) * 2;
    uint32_t b_base = smem_u32(Bs) + ((warp_n + (sub >> 1) * 8 + lrow) * PAD + (sub & 1) * 8) * 2;

    const int NCH = K >> 6;
    const int ld4 = K >> 3;
    for (int c = 0; c < NCH; c++) {
        const uint4* ag = (const uint4*)(A + (size_t)m0 * K + c * 64);
        const uint4* bg = (const uint4*)(B + (size_t)n0 * K + c * 64);
        #pragma unroll
        for (int p = 0; p < 4; p++) {
            int idx = p * 256 + tid;
            int row = idx >> 3, col = idx & 7;
            *(uint4*)&As[row * PAD + col * 8] = ag[(size_t)row * ld4 + col];
            *(uint4*)&Bs[row * PAD + col * 8] = bg[(size_t)row * ld4 + col];
        }
        __syncthreads();
        #pragma unroll
        for (int ks = 0; ks < 4; ks++) {
            uint32_t af[4][4], bf[2][4];
            #pragma unroll
            for (int mt = 0; mt < 4; mt++) ldsm4(af[mt], a_base + (mt * 16 * PAD + ks * 16) * 2);
            #pragma unroll
            for (int pr = 0; pr < 2; pr++) ldsm4(bf[pr], b_base + (pr * 16 * PAD + ks * 16) * 2);
            #pragma unroll
            for (int mt = 0; mt < 4; mt++) {
                mma_bf16(acc[mt][0], af[mt], &bf[0][0]);
                mma_bf16(acc[mt][1], af[mt], &bf[0][2]);
                mma_bf16(acc[mt][2], af[mt], &bf[1][0]);
                mma_bf16(acc[mt][3], af[mt], &bf[1][2]);
            }
        }
        __syncthreads();
    }

    int crow = lane >> 2, ccol = (lane & 3) * 2;
    #pragma unroll
    for (int mt = 0; mt < 4; mt++) {
        #pragma unroll
        for (int half = 0; half < 2; half++) {
            int m = m0 + warp_m + mt * 16 + crow + half * 8;
            if (m >= M) continue;
            #pragma unroll
            for (int nt = 0; nt < 4; nt++) {
                int n = n0 + warp_n + nt * 8 + ccol;
                float2 v;
                v.x = acc[mt][nt][half * 2 + 0] + bias[n];
                v.y = acc[mt][nt][half * 2 + 1] + bias[n + 1];
                if (residual) {
                    float2 rr = *(const float2*)(residual + (size_t)m * N + n);
                    v.x = rr.x + gain[n]     * v.x;
                    v.y = rr.y + gain[n + 1] * v.y;
                }
                *(float2*)(outp + (size_t)m * N + n) = v;
            }
        }
    }
}

// ---------------- fused FFN-up: h = silu(A@W1^T+b1)*(A@W2^T+b2) -> bf16 ----------------
// CTA tile 128(M) x 64(N), 8 warps (each 64x16 per weight), K chunk 64.
__global__ void __launch_bounds__(256) hmma_dual_kernel(
    const __nv_bfloat16* __restrict__ A,
    const __nv_bfloat16* __restrict__ B1, const float* __restrict__ b1,
    const __nv_bfloat16* __restrict__ B2, const float* __restrict__ b2,
    __nv_bfloat16* __restrict__ outp, int M, int N, int K)
{
    __shared__ __align__(16) uint16_t As [128 * PAD];
    __shared__ __align__(16) uint16_t B1s[64 * PAD];
    __shared__ __align__(16) uint16_t B2s[64 * PAD];
    int tid = threadIdx.x, lane = tid & 31, wid = tid >> 5;
    int m0 = blockIdx.y * 128, n0 = blockIdx.x * 64;
    int warp_m = (wid & 1) * 64, warp_n = (wid >> 1) * 16;

    float acc1[4][2][4] = {}, acc2[4][2][4] = {};

    int sub = lane >> 3, lrow = lane & 7;
    uint32_t a_base  = smem_u32(As)  + ((warp_m + (sub & 1) * 8 + lrow) * PAD + (sub >> 1) * 8) * 2;
    uint32_t b1_base = smem_u32(B1s) + ((warp_n + (sub >> 1) * 8 + lrow) * PAD + (sub & 1) * 8) * 2;
    uint32_t b2_base = smem_u32(B2s) + ((warp_n + (sub >> 1) * 8 + lrow) * PAD + (sub & 1) * 8) * 2;

    const int NCH = K >> 6;
    const int ld4 = K >> 3;
    for (int c = 0; c < NCH; c++) {
        const uint4* ag  = (const uint4*)(A  + (size_t)m0 * K + c * 64);
        const uint4* bg1 = (const uint4*)(B1 + (size_t)n0 * K + c * 64);
        const uint4* bg2 = (const uint4*)(B2 + (size_t)n0 * K + c * 64);
        #pragma unroll
        for (int p = 0; p < 4; p++) {
            int idx = p * 256 + tid;
            int row = idx >> 3, col = idx & 7;
            *(uint4*)&As[row * PAD + col * 8] = ag[(size_t)row * ld4 + col];
        }
        #pragma unroll
        for (int p = 0; p < 2; p++) {
            int idx = p * 256 + tid;
            int row = idx >> 3, col = idx & 7;
            *(uint4*)&B1s[row * PAD + col * 8] = bg1[(size_t)row * ld4 + col];
            *(uint4*)&B2s[row * PAD + col * 8] = bg2[(size_t)row * ld4 + col];
        }
        __syncthreads();
        #pragma unroll
        for (int ks = 0; ks < 4; ks++) {
            uint32_t af[4][4], bf1[4], bf2[4];
            #pragma unroll
            for (int mt = 0; mt < 4; mt++) ldsm4(af[mt], a_base + (mt * 16 * PAD + ks * 16) * 2);
            ldsm4(bf1, b1_base + (ks * 16) * 2);
            ldsm4(bf2, b2_base + (ks * 16) * 2);
            #pragma unroll
            for (int mt = 0; mt < 4; mt++) {
                mma_bf16(acc1[mt][0], af[mt], &bf1[0]);
                mma_bf16(acc1[mt][1], af[mt], &bf1[2]);
                mma_bf16(acc2[mt][0], af[mt], &bf2[0]);
                mma_bf16(acc2[mt][1], af[mt], &bf2[2]);
            }
        }
        __syncthreads();
    }

    int crow = lane >> 2, ccol = (lane & 3) * 2;
    #pragma unroll
    for (int mt = 0; mt < 4; mt++) {
        #pragma unroll
        for (int half = 0; half < 2; half++) {
            int m = m0 + warp_m + mt * 16 + crow + half * 8;
            if (m >= M) continue;
            #pragma unroll
            for (int nt = 0; nt < 2; nt++) {
                int n = n0 + warp_n + nt * 8 + ccol;
                float z0 = acc1[mt][nt][half * 2 + 0] + b1[n];
                float z1 = acc1[mt][nt][half * 2 + 1] + b1[n + 1];
                float g0 = acc2[mt][nt][half * 2 + 0] + b2[n];
                float g1 = acc2[mt][nt][half * 2 + 1] + b2[n + 1];
                float h0 = (z0 / (1.0f + __expf(-z0))) * g0;
                float h1 = (z1 / (1.0f + __expf(-z1))) * g1;
                *(__nv_bfloat162*)(outp + (size_t)m * N + n) = __floats2bfloat162_rn(h0, h1);
            }
        }
    }
}

// ---------------- deformable-attention sampling -> bf16 out ----------------
__global__ void __launch_bounds__(256) msda_kernel(
    const float* __restrict__ ref,   // (bs, Lq, NL, 2)
    const float* __restrict__ value, // (bs*Lq, 256) fp32
    const float* __restrict__ off,   // (bs*Lq, 256)
    const float* __restrict__ awl,   // (bs*Lq, 128) logits
    __nv_bfloat16* __restrict__ outp)
{
    int token = blockIdx.x;
    int h     = threadIdx.x >> 5;
    int lane  = threadIdx.x & 31;

    const float* aw = awl + (size_t)token * 128 + h * 16;
    const float* of = off + (size_t)token * 256 + h * 32;

    float wgt[16];
    float mx = -1e30f;
    #pragma unroll
    for (int s = 0; s < 16; s++) { wgt[s] = aw[s]; mx = fmaxf(mx, wgt[s]); }
    float sum = 0.f;
    #pragma unroll
    for (int s = 0; s < 16; s++) { wgt[s] = __expf(wgt[s] - mx); sum += wgt[s]; }
    float inv = 1.0f / sum;

    int b = token / LQ;
    const float* vb = value + (size_t)b * LQ * 256 + h * 32 + lane;

    float acc = 0.f;
    #pragma unroll
    for (int l = 0; l < 4; l++) {
        const int H  = c_H[l];
        const int W  = c_W[l];
        const int st = c_st[l];
        float rx = ref[(size_t)token * 8 + l * 2 + 0];
        float ry = ref[(size_t)token * 8 + l * 2 + 1];
        #pragma unroll
        for (int p = 0; p < 4; p++) {
            int s = l * 4 + p;
            float x = fmaf(rx, (float)W, of[s * 2 + 0] - 0.5f);
            float y = fmaf(ry, (float)H, of[s * 2 + 1] - 0.5f);
            float x0f = floorf(x), y0f = floorf(y);
            int   x0  = (int)x0f,  y0  = (int)y0f;
            float lx = x - x0f, ly = y - y0f;
            float ws  = wgt[s] * inv;
            float w00 = (1.f - lx) * (1.f - ly) * ws;
            float w01 = lx * (1.f - ly) * ws;
            float w10 = (1.f - lx) * ly * ws;
            float w11 = lx * ly * ws;
            bool x0v = (x0 >= 0)     && (x0 < W);
            bool x1v = (x0 + 1 >= 0) && (x0 + 1 < W);
            if (y0 >= 0 && y0 < H) {
                long long base = (long long)(st + y0 * W) * 256;
                if (x0v) acc += w00 * vb[base + (long long)x0 * 256];
                if (x1v) acc += w01 * vb[base + (long long)(x0 + 1) * 256];
            }
            int y1 = y0 + 1;
            if (y1 >= 0 && y1 < H) {
                long long base = (long long)(st + y1 * W) * 256;
                if (x0v) acc += w10 * vb[base + (long long)x0 * 256];
                if (x1v) acc += w11 * vb[base + (long long)(x0 + 1) * 256];
            }
        }
    }
    outp[(size_t)token * 256 + h * 32 + lane] = __float2bfloat16(acc);
}

// ---------------- host launch ----------------
template <typename T>
static T* symaddr(const void* sym) {
    void* p = nullptr;
    cudaGetSymbolAddress(&p, sym);
    return (T*)p;
}

extern "C" void kernel_launch(void* const* d_in, const int* in_sizes, int n_in,
                              void* d_out, int out_size) {
    (void)in_sizes; (void)n_in; (void)out_size;
    const float* query = (const float*)d_in[0];
    const float* qpos  = (const float*)d_in[1];
    const float* ref   = (const float*)d_in[2];
    const float* nw1   = (const float*)d_in[5];
    const float* Wv    = (const float*)d_in[6];
    const float* bv    = (const float*)d_in[7];
    const float* Woff  = (const float*)d_in[8];
    const float* boff  = (const float*)d_in[9];
    const float* Waw   = (const float*)d_in[10];
    const float* baw   = (const float*)d_in[11];
    const float* Wo    = (const float*)d_in[12];
    const float* bo    = (const float*)d_in[13];
    const float* lsa   = (const float*)d_in[14];
    const float* nw2   = (const float*)d_in[15];
    const float* W1    = (const float*)d_in[16];
    const float* b1    = (const float*)d_in[17];
    const float* W2    = (const float*)d_in[18];
    const float* b2    = (const float*)d_in[19];
    const float* W3    = (const float*)d_in[20];
    const float* b3    = (const float*)d_in[21];
    const float* lsf   = (const float*)d_in[22];
    float* out = (float*)d_out;

    __nv_bfloat16* nb    = symaddr<__nv_bfloat16>(g_nb);
    __nv_bfloat16* qb    = symaddr<__nv_bfloat16>(g_qb);
    float*         pval  = symaddr<float>(g_value);
    float*         poff  = symaddr<float>(g_off);
    float*         pawl  = symaddr<float>(g_awl);
    __nv_bfloat16* attnb = symaddr<__nv_bfloat16>(g_attnb);
    float*         px    = symaddr<float>(g_x);
    __nv_bfloat16* n2b   = symaddr<__nv_bfloat16>(g_n2b);
    __nv_bfloat16* hb    = symaddr<__nv_bfloat16>(g_hb);
    __nv_bfloat16* wb    = symaddr<__nv_bfloat16>(g_wb);

    // 0. weights -> bf16
    WSrc ws; ws.s[0] = Wv; ws.s[1] = Woff; ws.s[2] = Waw; ws.s[3] = Wo;
    ws.s[4] = W1; ws.s[5] = W2; ws.s[6] = W3;
    wconv_kernel<<<dim3(256, 7), 256>>>(ws);

    // 1. rmsnorm -> normed bf16, q = normed+pos bf16
    rmsnorm_kernel<<<(MTOK + 7) / 8, 256>>>(query, nw1, nb, qpos, qb);
    // 2-4. projection GEMMs
    hmma_gemm_kernel<<<dim3(2, MT128), 256>>>(nb, wb + WOFF_WV,   bv,   pval, MTOK, 256, 256, nullptr, nullptr);
    hmma_gemm_kernel<<<dim3(2, MT128), 256>>>(qb, wb + WOFF_WOFF, boff, poff, MTOK, 256, 256, nullptr, nullptr);
    hmma_gemm_kernel<<<dim3(1, MT128), 256>>>(qb, wb + WOFF_WAW,  baw,  pawl, MTOK, 128, 256, nullptr, nullptr);
    // 5. deformable sampling -> attn bf16
    msda_kernel<<<MTOK, 256>>>(ref, pval, poff, pawl, attnb);
    // 6. x = query + ls_attn * (attn @ Wo^T + bo)
    hmma_gemm_kernel<<<dim3(2, MT128), 256>>>(attnb, wb + WOFF_WO, bo, px, MTOK, 256, 256, query, lsa);
    // 7. n2 = rmsnorm(x) bf16
    rmsnorm_kernel<<<(MTOK + 7) / 8, 256>>>(px, nw2, n2b, nullptr, nullptr);
    // 8. h = silu(n2@W1^T+b1)*(n2@W2^T+b2) bf16
    hmma_dual_kernel<<<dim3(16, MT128), 256>>>(n2b, wb + WOFF_W1, b1, wb + WOFF_W2, b2, hb, MTOK, DFFN, 256);
    // 9. out = x + ls_ffn * (h @ W3^T + b3)
    hmma_gemm_kernel<<<dim3(2, MT128), 256>>>(hb, wb + WOFF_W3, b3, out, MTOK, 256, 1024, px, lsf);
}

// round 4
// speedup vs baseline: 3.0119x; 1.0500x over previous
#include <cuda_runtime.h>
#include <cuda_bf16.h>
#include <cstdint>
#include <math.h>

// ---------------- problem constants ----------------
#define BSZ   2
#define LQ    17821
#define CDIM  256
#define MTOK  (BSZ*LQ)          // 35642
#define MPAD  35712             // 279 * 128
#define MT128 279
#define DFFN  1024
#define PAD   72                // smem row stride in halves (144B, conflict-free)

__device__ __constant__ int c_H[4]  = {100, 50, 25, 13};
__device__ __constant__ int c_W[4]  = {134, 67, 34, 17};
__device__ __constant__ int c_st[4] = {0, 13400, 16750, 17600};

// ---------------- scratch (no allocs; zero-initialized .bss) ----------------
__device__ __nv_bfloat16 g_nb    [(size_t)MPAD*CDIM];
__device__ __nv_bfloat16 g_qb    [(size_t)MPAD*CDIM];
__device__ __nv_bfloat16 g_valueb[(size_t)MPAD*CDIM];
__device__ float         g_off   [(size_t)MTOK*CDIM];
__device__ float         g_awl   [(size_t)MTOK*128];
__device__ __nv_bfloat16 g_attnb [(size_t)MPAD*CDIM];
__device__ float         g_x     [(size_t)MTOK*CDIM];
__device__ __nv_bfloat16 g_n2b   [(size_t)MPAD*CDIM];
__device__ __nv_bfloat16 g_hb    [(size_t)MPAD*DFFN];
// converted weights: Wv,Woff,Waw,Wo,W1,W2,W3
#define WOFF_WV   0
#define WOFF_WOFF 65536
#define WOFF_WAW  131072
#define WOFF_WO   163840
#define WOFF_W1   229376
#define WOFF_W2   491520
#define WOFF_W3   753664
__device__ __nv_bfloat16 g_wb[1015808];

// ================= helpers =================
__device__ __forceinline__ uint32_t smem_u32(const void* p) {
    uint32_t a;
    asm("{ .reg .u64 t; cvta.to.shared.u64 t, %1; cvt.u32.u64 %0, t; }" : "=r"(a) : "l"(p));
    return a;
}
__device__ __forceinline__ void ldsm4(uint32_t* r, uint32_t addr) {
    asm volatile("ldmatrix.sync.aligned.m8n8.x4.shared.b16 {%0,%1,%2,%3}, [%4];"
        : "=r"(r[0]), "=r"(r[1]), "=r"(r[2]), "=r"(r[3]) : "r"(addr));
}
__device__ __forceinline__ void mma_bf16(float* c, const uint32_t* a, const uint32_t* b) {
    asm volatile(
        "mma.sync.aligned.m16n8k16.row.col.f32.bf16.bf16.f32 "
        "{%0,%1,%2,%3}, {%4,%5,%6,%7}, {%8,%9}, {%0,%1,%2,%3};"
        : "+f"(c[0]), "+f"(c[1]), "+f"(c[2]), "+f"(c[3])
        : "r"(a[0]), "r"(a[1]), "r"(a[2]), "r"(a[3]), "r"(b[0]), "r"(b[1]));
}
__device__ __forceinline__ void cp16(uint32_t dst, const void* src) {
    asm volatile("cp.async.ca.shared.global [%0], [%1], 16;" :: "r"(dst), "l"(src));
}
#define CP_COMMIT() asm volatile("cp.async.commit_group;" ::: "memory")
#define CP_WAIT1()  asm volatile("cp.async.wait_group 1;" ::: "memory")
#define CP_WAIT0()  asm volatile("cp.async.wait_group 0;" ::: "memory")

// ---------------- weight fp32 -> bf16 convert ----------------
struct WSrc { const float* s[7]; };
__device__ __constant__ int c_wsz [7] = {65536, 65536, 32768, 65536, 262144, 262144, 262144};
__device__ __constant__ int c_woff[7] = {WOFF_WV, WOFF_WOFF, WOFF_WAW, WOFF_WO, WOFF_W1, WOFF_W2, WOFF_W3};

__global__ void __launch_bounds__(256) wconv_kernel(WSrc w) {
    int seg = blockIdx.y;
    int i = (blockIdx.x * 256 + threadIdx.x) * 4;
    if (i >= c_wsz[seg]) return;
    float4 v = *(const float4*)(w.s[seg] + i);
    __nv_bfloat16* d = g_wb + c_woff[seg] + i;
    *(__nv_bfloat162*)(d)     = __floats2bfloat162_rn(v.x, v.y);
    *(__nv_bfloat162*)(d + 2) = __floats2bfloat162_rn(v.z, v.w);
}

// ---------------- RMSNorm -> bf16 (+ optional bf16 normed+addend) ----------------
__global__ void __launch_bounds__(256) rmsnorm_kernel(
    const float* __restrict__ x, const float* __restrict__ w,
    __nv_bfloat16* __restrict__ out, const float* __restrict__ addend,
    __nv_bfloat16* __restrict__ out2)
{
    int row  = blockIdx.x * 8 + (threadIdx.x >> 5);
    if (row >= MTOK) return;
    int lane = threadIdx.x & 31;
    const float4* xr = (const float4*)(x + (size_t)row * CDIM);
    float4 v0 = xr[lane];
    float4 v1 = xr[lane + 32];
    float ss = v0.x*v0.x + v0.y*v0.y + v0.z*v0.z + v0.w*v0.w
             + v1.x*v1.x + v1.y*v1.y + v1.z*v1.z + v1.w*v1.w;
    #pragma unroll
    for (int o = 16; o > 0; o >>= 1) ss += __shfl_xor_sync(0xffffffffu, ss, o);
    float s = rsqrtf(ss * (1.0f / CDIM) + 1e-6f);
    const float4* w4 = (const float4*)w;
    float4 g0 = w4[lane], g1 = w4[lane + 32];
    float n0x = v0.x*s*g0.x, n0y = v0.y*s*g0.y, n0z = v0.z*s*g0.z, n0w = v0.w*s*g0.w;
    float n1x = v1.x*s*g1.x, n1y = v1.y*s*g1.y, n1z = v1.z*s*g1.z, n1w = v1.w*s*g1.w;
    __nv_bfloat162* o2 = (__nv_bfloat162*)(out + (size_t)row * CDIM);
    o2[lane*2+0]  = __floats2bfloat162_rn(n0x, n0y);
    o2[lane*2+1]  = __floats2bfloat162_rn(n0z, n0w);
    o2[64+lane*2] = __floats2bfloat162_rn(n1x, n1y);
    o2[65+lane*2] = __floats2bfloat162_rn(n1z, n1w);
    if (out2) {
        const float4* a4 = (const float4*)(addend + (size_t)row * CDIM);
        float4 p0 = a4[lane], p1 = a4[lane + 32];
        __nv_bfloat162* q2 = (__nv_bfloat162*)(out2 + (size_t)row * CDIM);
        q2[lane*2+0]  = __floats2bfloat162_rn(n0x + p0.x, n0y + p0.y);
        q2[lane*2+1]  = __floats2bfloat162_rn(n0z + p0.z, n0w + p0.w);
        q2[64+lane*2] = __floats2bfloat162_rn(n1x + p1.x, n1y + p1.y);
        q2[65+lane*2] = __floats2bfloat162_rn(n1z + p1.z, n1w + p1.w);
    }
}

// ---------------- HMMA GEMM, cp.async 2-stage pipeline ----------------
// out[m,n] = sum_k A[m,k]*B[n,k] + bias[n]
// optional: out = residual + gain[n]*(acc+bias);  optional bf16 output (outb)
// CTA tile 128x128, 8 warps (64x32 each), K chunk 64.
#define TILE_BYTES  (128 * PAD * 2)     // 18432
#define STAGE_BYTES (2 * TILE_BYTES)    // 36864: [As | Bs]

__global__ void __launch_bounds__(256) hmma_gemm_kernel(
    const __nv_bfloat16* __restrict__ A, const __nv_bfloat16* __restrict__ B,
    const float* __restrict__ bias, float* __restrict__ outp,
    __nv_bfloat16* __restrict__ outb,
    int M, int N, int K,
    const float* __restrict__ residual, const float* __restrict__ gain)
{
    extern __shared__ __align__(16) char smem[];
    uint32_t sb = smem_u32(smem);
    int tid = threadIdx.x, lane = tid & 31, wid = tid >> 5;
    int m0 = blockIdx.y * 128, n0 = blockIdx.x * 128;
    int warp_m = (wid & 1) * 64, warp_n = (wid >> 1) * 32;

    float acc[4][4][4] = {};

    int sub = lane >> 3, lrow = lane & 7;
    uint32_t a_off = ((warp_m + (sub & 1) * 8 + lrow) * PAD + (sub >> 1) * 8) * 2;
    uint32_t b_off = TILE_BYTES + ((warp_n + (sub >> 1) * 8 + lrow) * PAD + (sub & 1) * 8) * 2;

    const int NCH = K >> 6;
    const int ld4 = K >> 3;
    int lrow4 = tid >> 3, lcol4 = tid & 7;   // loader: row, 16B col
    const uint4* agl = (const uint4*)(A + (size_t)m0 * K) + (size_t)lrow4 * ld4 + lcol4;
    const uint4* bgl = (const uint4*)(B + (size_t)n0 * K) + (size_t)lrow4 * ld4 + lcol4;
    uint32_t sdst = sb + lrow4 * (PAD * 2) + lcol4 * 16;

    // prologue: stage 0
    #pragma unroll
    for (int p = 0; p < 4; p++) {
        cp16(sdst + p * 32 * (PAD * 2),              agl + (size_t)p * 32 * ld4);
        cp16(sdst + TILE_BYTES + p * 32 * (PAD * 2), bgl + (size_t)p * 32 * ld4);
    }
    CP_COMMIT();

    for (int c = 0; c < NCH; c++) {
        int buf = c & 1;
        if (c + 1 < NCH) {
            int nbuf = (c + 1) & 1;
            const uint4* ag = agl + (size_t)(c + 1) * 8;
            const uint4* bg = bgl + (size_t)(c + 1) * 8;
            uint32_t d = sdst + nbuf * STAGE_BYTES;
            #pragma unroll
            for (int p = 0; p < 4; p++) {
                cp16(d + p * 32 * (PAD * 2),              ag + (size_t)p * 32 * ld4);
                cp16(d + TILE_BYTES + p * 32 * (PAD * 2), bg + (size_t)p * 32 * ld4);
            }
            CP_COMMIT();
            CP_WAIT1();
        } else {
            CP_WAIT0();
        }
        __syncthreads();
        uint32_t ab = sb + buf * STAGE_BYTES + a_off;
        uint32_t bb = sb + buf * STAGE_BYTES + b_off;
        #pragma unroll
        for (int ks = 0; ks < 4; ks++) {
            uint32_t af[4][4], bf[2][4];
            #pragma unroll
            for (int mt = 0; mt < 4; mt++) ldsm4(af[mt], ab + (mt * 16 * PAD + ks * 16) * 2);
            #pragma unroll
            for (int pr = 0; pr < 2; pr++) ldsm4(bf[pr], bb + (pr * 16 * PAD + ks * 16) * 2);
            #pragma unroll
            for (int mt = 0; mt < 4; mt++) {
                mma_bf16(acc[mt][0], af[mt], &bf[0][0]);
                mma_bf16(acc[mt][1], af[mt], &bf[0][2]);
                mma_bf16(acc[mt][2], af[mt], &bf[1][0]);
                mma_bf16(acc[mt][3], af[mt], &bf[1][2]);
            }
        }
        __syncthreads();
    }

    int crow = lane >> 2, ccol = (lane & 3) * 2;
    #pragma unroll
    for (int mt = 0; mt < 4; mt++) {
        #pragma unroll
        for (int half = 0; half < 2; half++) {
            int m = m0 + warp_m + mt * 16 + crow + half * 8;
            if (m >= M) continue;
            #pragma unroll
            for (int nt = 0; nt < 4; nt++) {
                int n = n0 + warp_n + nt * 8 + ccol;
                float vx = acc[mt][nt][half * 2 + 0] + bias[n];
                float vy = acc[mt][nt][half * 2 + 1] + bias[n + 1];
                if (residual) {
                    float2 rr = *(const float2*)(residual + (size_t)m * N + n);
                    vx = rr.x + gain[n]     * vx;
                    vy = rr.y + gain[n + 1] * vy;
                }
                if (outb) {
                    *(__nv_bfloat162*)(outb + (size_t)m * N + n) = __floats2bfloat162_rn(vx, vy);
                } else {
                    *(float2*)(outp + (size_t)m * N + n) = make_float2(vx, vy);
                }
            }
        }
    }
}

// ---------------- fused FFN-up, cp.async 2-stage ----------------
// h = silu(A@W1^T+b1)*(A@W2^T+b2) -> bf16.  CTA tile 128(M) x 64(N).
#define DTILE_A  (128 * PAD * 2)                    // 18432
#define DTILE_B  (64 * PAD * 2)                     // 9216
#define DSTAGE   (DTILE_A + 2 * DTILE_B)            // 36864

__global__ void __launch_bounds__(256) hmma_dual_kernel(
    const __nv_bfloat16* __restrict__ A,
    const __nv_bfloat16* __restrict__ B1, const float* __restrict__ b1,
    const __nv_bfloat16* __restrict__ B2, const float* __restrict__ b2,
    __nv_bfloat16* __restrict__ outp, int M, int N, int K)
{
    extern __shared__ __align__(16) char smem[];
    uint32_t sb = smem_u32(smem);
    int tid = threadIdx.x, lane = tid & 31, wid = tid >> 5;
    int m0 = blockIdx.y * 128, n0 = blockIdx.x * 64;
    int warp_m = (wid & 1) * 64, warp_n = (wid >> 1) * 16;

    float acc1[4][2][4] = {}, acc2[4][2][4] = {};

    int sub = lane >> 3, lrow = lane & 7;
    uint32_t a_off  = ((warp_m + (sub & 1) * 8 + lrow) * PAD + (sub >> 1) * 8) * 2;
    uint32_t b1_off = DTILE_A + ((warp_n + (sub >> 1) * 8 + lrow) * PAD + (sub & 1) * 8) * 2;
    uint32_t b2_off = DTILE_A + DTILE_B + ((warp_n + (sub >> 1) * 8 + lrow) * PAD + (sub & 1) * 8) * 2;

    const int NCH = K >> 6;
    const int ld4 = K >> 3;
    int lrow4 = tid >> 3, lcol4 = tid & 7;
    const uint4* agl  = (const uint4*)(A  + (size_t)m0 * K) + (size_t)lrow4 * ld4 + lcol4;
    const uint4* bgl1 = (const uint4*)(B1 + (size_t)n0 * K) + (size_t)lrow4 * ld4 + lcol4;
    const uint4* bgl2 = (const uint4*)(B2 + (size_t)n0 * K) + (size_t)lrow4 * ld4 + lcol4;
    uint32_t sdst = sb + lrow4 * (PAD * 2) + lcol4 * 16;
    bool bload = (lrow4 < 64);

    #pragma unroll
    for (int p = 0; p < 4; p++)
        cp16(sdst + p * 32 * (PAD * 2), agl + (size_t)p * 32 * ld4);
    if (bload) {
        cp16(sdst + DTILE_A,               bgl1);
        cp16(sdst + DTILE_A + 32*(PAD*2),  bgl1 + (size_t)32 * ld4);
        cp16(sdst + DTILE_A + DTILE_B,              bgl2);
        cp16(sdst + DTILE_A + DTILE_B + 32*(PAD*2), bgl2 + (size_t)32 * ld4);
    }
    CP_COMMIT();

    for (int c = 0; c < NCH; c++) {
        int buf = c & 1;
        if (c + 1 < NCH) {
            int nbuf = (c + 1) & 1;
            uint32_t d = sdst + nbuf * DSTAGE;
            const uint4* ag  = agl  + (size_t)(c + 1) * 8;
            #pragma unroll
            for (int p = 0; p < 4; p++)
                cp16(d + p * 32 * (PAD * 2), ag + (size_t)p * 32 * ld4);
            if (bload) {
                const uint4* bg1 = bgl1 + (size_t)(c + 1) * 8;
                const uint4* bg2 = bgl2 + (size_t)(c + 1) * 8;
                cp16(d + DTILE_A,              bg1);
                cp16(d + DTILE_A + 32*(PAD*2), bg1 + (size_t)32 * ld4);
                cp16(d + DTILE_A + DTILE_B,              bg2);
                cp16(d + DTILE_A + DTILE_B + 32*(PAD*2), bg2 + (size_t)32 * ld4);
            }
            CP_COMMIT();
            CP_WAIT1();
        } else {
            CP_WAIT0();
        }
        __syncthreads();
        uint32_t ab  = sb + buf * DSTAGE + a_off;
        uint32_t bb1 = sb + buf * DSTAGE + b1_off;
        uint32_t bb2 = sb + buf * DSTAGE + b2_off;
        #pragma unroll
        for (int ks = 0; ks < 4; ks++) {
            uint32_t af[4][4], bf1[4], bf2[4];
            #pragma unroll
            for (int mt = 0; mt < 4; mt++) ldsm4(af[mt], ab + (mt * 16 * PAD + ks * 16) * 2);
            ldsm4(bf1, bb1 + (ks * 16) * 2);
            ldsm4(bf2, bb2 + (ks * 16) * 2);
            #pragma unroll
            for (int mt = 0; mt < 4; mt++) {
                mma_bf16(acc1[mt][0], af[mt], &bf1[0]);
                mma_bf16(acc1[mt][1], af[mt], &bf1[2]);
                mma_bf16(acc2[mt][0], af[mt], &bf2[0]);
                mma_bf16(acc2[mt][1], af[mt], &bf2[2]);
            }
        }
        __syncthreads();
    }

    int crow = lane >> 2, ccol = (lane & 3) * 2;
    #pragma unroll
    for (int mt = 0; mt < 4; mt++) {
        #pragma unroll
        for (int half = 0; half < 2; half++) {
            int m = m0 + warp_m + mt * 16 + crow + half * 8;
            if (m >= M) continue;
            #pragma unroll
            for (int nt = 0; nt < 2; nt++) {
                int n = n0 + warp_n + nt * 8 + ccol;
                float z0 = acc1[mt][nt][half * 2 + 0] + b1[n];
                float z1 = acc1[mt][nt][half * 2 + 1] + b1[n + 1];
                float g0 = acc2[mt][nt][half * 2 + 0] + b2[n];
                float g1 = acc2[mt][nt][half * 2 + 1] + b2[n + 1];
                float h0 = (z0 / (1.0f + __expf(-z0))) * g0;
                float h1 = (z1 / (1.0f + __expf(-z1))) * g1;
                *(__nv_bfloat162*)(outp + (size_t)m * N + n) = __floats2bfloat162_rn(h0, h1);
            }
        }
    }
}

// ---------------- deformable-attention sampling (bf16 value) -> bf16 out ----------------
__global__ void __launch_bounds__(256) msda_kernel(
    const float* __restrict__ ref,             // (bs, Lq, NL, 2)
    const __nv_bfloat16* __restrict__ value,   // (bs*Lq, 256) bf16
    const float* __restrict__ off,             // (bs*Lq, 256)
    const float* __restrict__ awl,             // (bs*Lq, 128) logits
    __nv_bfloat16* __restrict__ outp)
{
    int token = blockIdx.x;
    int h     = threadIdx.x >> 5;
    int lane  = threadIdx.x & 31;

    const float* aw = awl + (size_t)token * 128 + h * 16;
    const float* of = off + (size_t)token * 256 + h * 32;

    float wgt[16];
    float mx = -1e30f;
    #pragma unroll
    for (int s = 0; s < 16; s++) { wgt[s] = aw[s]; mx = fmaxf(mx, wgt[s]); }
    float sum = 0.f;
    #pragma unroll
    for (int s = 0; s < 16; s++) { wgt[s] = __expf(wgt[s] - mx); sum += wgt[s]; }
    float inv = 1.0f / sum;

    int b = token / LQ;
    const __nv_bfloat16* vb = value + (size_t)b * LQ * 256 + h * 32 + lane;

    float acc = 0.f;
    #pragma unroll
    for (int l = 0; l < 4; l++) {
        const int H  = c_H[l];
        const int W  = c_W[l];
        const int st = c_st[l];
        float rx = ref[(size_t)token * 8 + l * 2 + 0];
        float ry = ref[(size_t)token * 8 + l * 2 + 1];
        #pragma unroll
        for (int p = 0; p < 4; p++) {
            int s = l * 4 + p;
            float x = fmaf(rx, (float)W, of[s * 2 + 0] - 0.5f);
            float y = fmaf(ry, (float)H, of[s * 2 + 1] - 0.5f);
            float x0f = floorf(x), y0f = floorf(y);
            int   x0  = (int)x0f,  y0  = (int)y0f;
            float lx = x - x0f, ly = y - y0f;
            float ws  = wgt[s] * inv;
            float w00 = (1.f - lx) * (1.f - ly) * ws;
            float w01 = lx * (1.f - ly) * ws;
            float w10 = (1.f - lx) * ly * ws;
            float w11 = lx * ly * ws;
            bool x0v = (x0 >= 0)     && (x0 < W);
            bool x1v = (x0 + 1 >= 0) && (x0 + 1 < W);
            if (y0 >= 0 && y0 < H) {
                long long base = (long long)(st + y0 * W) * 256;
                if (x0v) acc += w00 * __bfloat162float(vb[base + (long long)x0 * 256]);
                if (x1v) acc += w01 * __bfloat162float(vb[base + (long long)(x0 + 1) * 256]);
            }
            int y1 = y0 + 1;
            if (y1 >= 0 && y1 < H) {
                long long base = (long long)(st + y1 * W) * 256;
                if (x0v) acc += w10 * __bfloat162float(vb[base + (long long)x0 * 256]);
                if (x1v) acc += w11 * __bfloat162float(vb[base + (long long)(x0 + 1) * 256]);
            }
        }
    }
    outp[(size_t)token * 256 + h * 32 + lane] = __float2bfloat16(acc);
}

// ---------------- host launch ----------------
template <typename T>
static T* symaddr(const void* sym) {
    void* p = nullptr;
    cudaGetSymbolAddress(&p, sym);
    return (T*)p;
}

extern "C" void kernel_launch(void* const* d_in, const int* in_sizes, int n_in,
                              void* d_out, int out_size) {
    (void)in_sizes; (void)n_in; (void)out_size;
    const float* query = (const float*)d_in[0];
    const float* qpos  = (const float*)d_in[1];
    const float* ref   = (const float*)d_in[2];
    const float* nw1   = (const float*)d_in[5];
    const float* Wv    = (const float*)d_in[6];
    const float* bv    = (const float*)d_in[7];
    const float* Woff  = (const float*)d_in[8];
    const float* boff  = (const float*)d_in[9];
    const float* Waw   = (const float*)d_in[10];
    const float* baw   = (const float*)d_in[11];
    const float* Wo    = (const float*)d_in[12];
    const float* bo    = (const float*)d_in[13];
    const float* lsa   = (const float*)d_in[14];
    const float* nw2   = (const float*)d_in[15];
    const float* W1    = (const float*)d_in[16];
    const float* b1    = (const float*)d_in[17];
    const float* W2    = (const float*)d_in[18];
    const float* b2    = (const float*)d_in[19];
    const float* W3    = (const float*)d_in[20];
    const float* b3    = (const float*)d_in[21];
    const float* lsf   = (const float*)d_in[22];
    float* out = (float*)d_out;

    __nv_bfloat16* nb    = symaddr<__nv_bfloat16>(g_nb);
    __nv_bfloat16* qb    = symaddr<__nv_bfloat16>(g_qb);
    __nv_bfloat16* valb  = symaddr<__nv_bfloat16>(g_valueb);
    float*         poff  = symaddr<float>(g_off);
    float*         pawl  = symaddr<float>(g_awl);
    __nv_bfloat16* attnb = symaddr<__nv_bfloat16>(g_attnb);
    float*         px    = symaddr<float>(g_x);
    __nv_bfloat16* n2b   = symaddr<__nv_bfloat16>(g_n2b);
    __nv_bfloat16* hb    = symaddr<__nv_bfloat16>(g_hb);
    __nv_bfloat16* wb    = symaddr<__nv_bfloat16>(g_wb);

    const int GSM = 2 * STAGE_BYTES;   // 73728
    const int DSM = 2 * DSTAGE;        // 73728
    cudaFuncSetAttribute(hmma_gemm_kernel, cudaFuncAttributeMaxDynamicSharedMemorySize, GSM);
    cudaFuncSetAttribute(hmma_dual_kernel, cudaFuncAttributeMaxDynamicSharedMemorySize, DSM);

    // 0. weights -> bf16
    WSrc ws; ws.s[0] = Wv; ws.s[1] = Woff; ws.s[2] = Waw; ws.s[3] = Wo;
    ws.s[4] = W1; ws.s[5] = W2; ws.s[6] = W3;
    wconv_kernel<<<dim3(256, 7), 256>>>(ws);

    // 1. rmsnorm -> normed bf16, q = normed+pos bf16
    rmsnorm_kernel<<<(MTOK + 7) / 8, 256>>>(query, nw1, nb, qpos, qb);
    // 2-4. projection GEMMs (value directly bf16)
    hmma_gemm_kernel<<<dim3(2, MT128), 256, GSM>>>(nb, wb + WOFF_WV,   bv,   nullptr, valb, MTOK, 256, 256, nullptr, nullptr);
    hmma_gemm_kernel<<<dim3(2, MT128), 256, GSM>>>(qb, wb + WOFF_WOFF, boff, poff, nullptr, MTOK, 256, 256, nullptr, nullptr);
    hmma_gemm_kernel<<<dim3(1, MT128), 256, GSM>>>(qb, wb + WOFF_WAW,  baw,  pawl, nullptr, MTOK, 128, 256, nullptr, nullptr);
    // 5. deformable sampling -> attn bf16
    msda_kernel<<<MTOK, 256>>>(ref, valb, poff, pawl, attnb);
    // 6. x = query + ls_attn * (attn @ Wo^T + bo)
    hmma_gemm_kernel<<<dim3(2, MT128), 256, GSM>>>(attnb, wb + WOFF_WO, bo, px, nullptr, MTOK, 256, 256, query, lsa);
    // 7. n2 = rmsnorm(x) bf16
    rmsnorm_kernel<<<(MTOK + 7) / 8, 256>>>(px, nw2, n2b, nullptr, nullptr);
    // 8. h = silu(n2@W1^T+b1)*(n2@W2^T+b2) bf16
    hmma_dual_kernel<<<dim3(16, MT128), 256, DSM>>>(n2b, wb + WOFF_W1, b1, wb + WOFF_W2, b2, hb, MTOK, DFFN, 256);
    // 9. out = x + ls_ffn * (h @ W3^T + b3)
    hmma_gemm_kernel<<<dim3(2, MT128), 256, GSM>>>(hb, wb + WOFF_W3, b3, out, nullptr, MTOK, 256, 1024, px, lsf);
}

// round 5
// speedup vs baseline: 3.6684x; 1.2180x over previous
#include <cuda_runtime.h>
#include <cuda_bf16.h>
#include <cstdint>
#include <math.h>

// ---------------- problem constants ----------------
#define BSZ   2
#define LQ    17821
#define CDIM  256
#define MTOK  (BSZ*LQ)          // 35642
#define MPAD  35712             // 279 * 128
#define MT128 279
#define DFFN  1024
#define PAD   72                // smem row stride in halves (144B, conflict-free)

__device__ __constant__ int c_H[4]  = {100, 50, 25, 13};
__device__ __constant__ int c_W[4]  = {134, 67, 34, 17};
__device__ __constant__ int c_st[4] = {0, 13400, 16750, 17600};

// ---------------- scratch (no allocs; zero-initialized .bss) ----------------
__device__ __nv_bfloat16 g_nb    [(size_t)MPAD*CDIM];
__device__ __nv_bfloat16 g_qb    [(size_t)MPAD*CDIM];
__device__ __nv_bfloat16 g_valueb[(size_t)MPAD*CDIM];
__device__ float         g_off   [(size_t)MTOK*CDIM];
__device__ float         g_awl   [(size_t)MTOK*128];
__device__ __nv_bfloat16 g_attnb [(size_t)MPAD*CDIM];
__device__ float         g_x     [(size_t)MTOK*CDIM];
__device__ __nv_bfloat16 g_n2b   [(size_t)MPAD*CDIM];
__device__ __nv_bfloat16 g_hb    [(size_t)MPAD*DFFN];
// converted weights: Wv,Woff,Waw,Wo,W1,W2,W3  (Woff and Waw contiguous -> fused (384,256))
#define WOFF_WV   0
#define WOFF_WOFF 65536
#define WOFF_WAW  131072
#define WOFF_WO   163840
#define WOFF_W1   229376
#define WOFF_W2   491520
#define WOFF_W3   753664
__device__ __nv_bfloat16 g_wb[1015808];

// ================= helpers =================
__device__ __forceinline__ uint32_t smem_u32(const void* p) {
    uint32_t a;
    asm("{ .reg .u64 t; cvta.to.shared.u64 t, %1; cvt.u32.u64 %0, t; }" : "=r"(a) : "l"(p));
    return a;
}
__device__ __forceinline__ void ldsm4(uint32_t* r, uint32_t addr) {
    asm volatile("ldmatrix.sync.aligned.m8n8.x4.shared.b16 {%0,%1,%2,%3}, [%4];"
        : "=r"(r[0]), "=r"(r[1]), "=r"(r[2]), "=r"(r[3]) : "r"(addr));
}
__device__ __forceinline__ void mma_bf16(float* c, const uint32_t* a, const uint32_t* b) {
    asm volatile(
        "mma.sync.aligned.m16n8k16.row.col.f32.bf16.bf16.f32 "
        "{%0,%1,%2,%3}, {%4,%5,%6,%7}, {%8,%9}, {%0,%1,%2,%3};"
        : "+f"(c[0]), "+f"(c[1]), "+f"(c[2]), "+f"(c[3])
        : "r"(a[0]), "r"(a[1]), "r"(a[2]), "r"(a[3]), "r"(b[0]), "r"(b[1]));
}
__device__ __forceinline__ void cp16(uint32_t dst, const void* src) {
    asm volatile("cp.async.ca.shared.global [%0], [%1], 16;" :: "r"(dst), "l"(src));
}
#define CP_COMMIT() asm volatile("cp.async.commit_group;" ::: "memory")
#define CP_WAIT1()  asm volatile("cp.async.wait_group 1;" ::: "memory")
#define CP_WAIT0()  asm volatile("cp.async.wait_group 0;" ::: "memory")

// ---------------- weight fp32 -> bf16 convert ----------------
struct WSrc { const float* s[7]; };
__device__ __constant__ int c_wsz [7] = {65536, 65536, 32768, 65536, 262144, 262144, 262144};
__device__ __constant__ int c_woff[7] = {WOFF_WV, WOFF_WOFF, WOFF_WAW, WOFF_WO, WOFF_W1, WOFF_W2, WOFF_W3};

__global__ void __launch_bounds__(256) wconv_kernel(WSrc w) {
    int seg = blockIdx.y;
    int i = (blockIdx.x * 256 + threadIdx.x) * 4;
    if (i >= c_wsz[seg]) return;
    float4 v = *(const float4*)(w.s[seg] + i);
    __nv_bfloat16* d = g_wb + c_woff[seg] + i;
    *(__nv_bfloat162*)(d)     = __floats2bfloat162_rn(v.x, v.y);
    *(__nv_bfloat162*)(d + 2) = __floats2bfloat162_rn(v.z, v.w);
}

// ---------------- RMSNorm -> bf16 (+ optional bf16 normed+addend) ----------------
__global__ void __launch_bounds__(256) rmsnorm_kernel(
    const float* __restrict__ x, const float* __restrict__ w,
    __nv_bfloat16* __restrict__ out, const float* __restrict__ addend,
    __nv_bfloat16* __restrict__ out2)
{
    int row  = blockIdx.x * 8 + (threadIdx.x >> 5);
    if (row >= MTOK) return;
    int lane = threadIdx.x & 31;
    const float4* xr = (const float4*)(x + (size_t)row * CDIM);
    float4 v0 = xr[lane];
    float4 v1 = xr[lane + 32];
    float ss = v0.x*v0.x + v0.y*v0.y + v0.z*v0.z + v0.w*v0.w
             + v1.x*v1.x + v1.y*v1.y + v1.z*v1.z + v1.w*v1.w;
    #pragma unroll
    for (int o = 16; o > 0; o >>= 1) ss += __shfl_xor_sync(0xffffffffu, ss, o);
    float s = rsqrtf(ss * (1.0f / CDIM) + 1e-6f);
    const float4* w4 = (const float4*)w;
    float4 g0 = w4[lane], g1 = w4[lane + 32];
    float n0x = v0.x*s*g0.x, n0y = v0.y*s*g0.y, n0z = v0.z*s*g0.z, n0w = v0.w*s*g0.w;
    float n1x = v1.x*s*g1.x, n1y = v1.y*s*g1.y, n1z = v1.z*s*g1.z, n1w = v1.w*s*g1.w;
    __nv_bfloat162* o2 = (__nv_bfloat162*)(out + (size_t)row * CDIM);
    o2[lane*2+0]  = __floats2bfloat162_rn(n0x, n0y);
    o2[lane*2+1]  = __floats2bfloat162_rn(n0z, n0w);
    o2[64+lane*2] = __floats2bfloat162_rn(n1x, n1y);
    o2[65+lane*2] = __floats2bfloat162_rn(n1z, n1w);
    if (out2) {
        const float4* a4 = (const float4*)(addend + (size_t)row * CDIM);
        float4 p0 = a4[lane], p1 = a4[lane + 32];
        __nv_bfloat162* q2 = (__nv_bfloat162*)(out2 + (size_t)row * CDIM);
        q2[lane*2+0]  = __floats2bfloat162_rn(n0x + p0.x, n0y + p0.y);
        q2[lane*2+1]  = __floats2bfloat162_rn(n0z + p0.z, n0w + p0.w);
        q2[64+lane*2] = __floats2bfloat162_rn(n1x + p1.x, n1y + p1.y);
        q2[65+lane*2] = __floats2bfloat162_rn(n1z + p1.z, n1w + p1.w);
    }
}

// ---------------- HMMA GEMM, 3-stage cp.async ring ----------------
// out[m,n] = sum_k A[m,k]*B[n,k] + bias[n], n in [0,N1); split tail to outp2 (stride N-N1,
// bias2) for n >= N1. optional residual+gain epilogue (N1==N only); optional bf16 out.
// CTA tile 128x128, 8 warps (64x32 each), K chunk 64.
#define TILE_BYTES  (128 * PAD * 2)     // 18432
#define STAGE_BYTES (2 * TILE_BYTES)    // 36864: [As | Bs]
#define NSTAGE 3

__global__ void __launch_bounds__(256) hmma_gemm_kernel(
    const __nv_bfloat16* __restrict__ A, const __nv_bfloat16* __restrict__ B,
    const float* __restrict__ bias, const float* __restrict__ bias2,
    float* __restrict__ outp, float* __restrict__ outp2,
    __nv_bfloat16* __restrict__ outb,
    int M, int N, int N1, int K,
    const float* __restrict__ residual, const float* __restrict__ gain)
{
    extern __shared__ __align__(16) char smem[];
    uint32_t sb = smem_u32(smem);
    int tid = threadIdx.x, lane = tid & 31, wid = tid >> 5;
    int m0 = blockIdx.y * 128, n0 = blockIdx.x * 128;
    int warp_m = (wid & 1) * 64, warp_n = (wid >> 1) * 32;

    float acc[4][4][4] = {};

    int sub = lane >> 3, lrow = lane & 7;
    uint32_t a_off = ((warp_m + (sub & 1) * 8 + lrow) * PAD + (sub >> 1) * 8) * 2;
    uint32_t b_off = TILE_BYTES + ((warp_n + (sub >> 1) * 8 + lrow) * PAD + (sub & 1) * 8) * 2;

    const int NCH = K >> 6;
    const int ld4 = K >> 3;
    int lrow4 = tid >> 3, lcol4 = tid & 7;
    const uint4* agl = (const uint4*)(A + (size_t)m0 * K) + (size_t)lrow4 * ld4 + lcol4;
    const uint4* bgl = (const uint4*)(B + (size_t)n0 * K) + (size_t)lrow4 * ld4 + lcol4;
    uint32_t sdst = sb + lrow4 * (PAD * 2) + lcol4 * 16;

    // prologue: stages 0,1
    #pragma unroll
    for (int s = 0; s < 2; s++) {
        if (s < NCH) {
            uint32_t d = sdst + s * STAGE_BYTES;
            const uint4* ag = agl + (size_t)s * 8;
            const uint4* bg = bgl + (size_t)s * 8;
            #pragma unroll
            for (int p = 0; p < 4; p++) {
                cp16(d + p * 32 * (PAD * 2),              ag + (size_t)p * 32 * ld4);
                cp16(d + TILE_BYTES + p * 32 * (PAD * 2), bg + (size_t)p * 32 * ld4);
            }
        }
        CP_COMMIT();
    }

    int stage = 0, lstage = 2;
    for (int c = 0; c < NCH; c++) {
        if (c + 1 < NCH) CP_WAIT1(); else CP_WAIT0();
        __syncthreads();
        if (c + 2 < NCH) {
            uint32_t d = sdst + lstage * STAGE_BYTES;
            const uint4* ag = agl + (size_t)(c + 2) * 8;
            const uint4* bg = bgl + (size_t)(c + 2) * 8;
            #pragma unroll
            for (int p = 0; p < 4; p++) {
                cp16(d + p * 32 * (PAD * 2),              ag + (size_t)p * 32 * ld4);
                cp16(d + TILE_BYTES + p * 32 * (PAD * 2), bg + (size_t)p * 32 * ld4);
            }
            CP_COMMIT();
            if (++lstage == NSTAGE) lstage = 0;
        }
        uint32_t ab = sb + stage * STAGE_BYTES + a_off;
        uint32_t bb = sb + stage * STAGE_BYTES + b_off;
        #pragma unroll
        for (int ks = 0; ks < 4; ks++) {
            uint32_t af[4][4], bf[2][4];
            #pragma unroll
            for (int mt = 0; mt < 4; mt++) ldsm4(af[mt], ab + (mt * 16 * PAD + ks * 16) * 2);
            #pragma unroll
            for (int pr = 0; pr < 2; pr++) ldsm4(bf[pr], bb + (pr * 16 * PAD + ks * 16) * 2);
            #pragma unroll
            for (int mt = 0; mt < 4; mt++) {
                mma_bf16(acc[mt][0], af[mt], &bf[0][0]);
                mma_bf16(acc[mt][1], af[mt], &bf[0][2]);
                mma_bf16(acc[mt][2], af[mt], &bf[1][0]);
                mma_bf16(acc[mt][3], af[mt], &bf[1][2]);
            }
        }
        if (++stage == NSTAGE) stage = 0;
    }

    int crow = lane >> 2, ccol = (lane & 3) * 2;
    #pragma unroll
    for (int mt = 0; mt < 4; mt++) {
        #pragma unroll
        for (int half = 0; half < 2; half++) {
            int m = m0 + warp_m + mt * 16 + crow + half * 8;
            if (m >= M) continue;
            #pragma unroll
            for (int nt = 0; nt < 4; nt++) {
                int n = n0 + warp_n + nt * 8 + ccol;
                if (n < N1) {
                    float vx = acc[mt][nt][half * 2 + 0] + bias[n];
                    float vy = acc[mt][nt][half * 2 + 1] + bias[n + 1];
                    if (residual) {
                        float2 rr = *(const float2*)(residual + (size_t)m * N1 + n);
                        vx = rr.x + gain[n]     * vx;
                        vy = rr.y + gain[n + 1] * vy;
                    }
                    if (outb) {
                        *(__nv_bfloat162*)(outb + (size_t)m * N1 + n) = __floats2bfloat162_rn(vx, vy);
                    } else {
                        *(float2*)(outp + (size_t)m * N1 + n) = make_float2(vx, vy);
                    }
                } else {
                    int S2 = N - N1, n2 = n - N1;
                    float vx = acc[mt][nt][half * 2 + 0] + bias2[n2];
                    float vy = acc[mt][nt][half * 2 + 1] + bias2[n2 + 1];
                    *(float2*)(outp2 + (size_t)m * S2 + n2) = make_float2(vx, vy);
                }
            }
        }
    }
}

// ---------------- fused FFN-up, 3-stage cp.async ring ----------------
// h = silu(A@W1^T+b1)*(A@W2^T+b2) -> bf16.  CTA tile 128(M) x 64(N).
#define DTILE_A  (128 * PAD * 2)                    // 18432
#define DTILE_B  (64 * PAD * 2)                     // 9216
#define DSTAGE   (DTILE_A + 2 * DTILE_B)            // 36864

__global__ void __launch_bounds__(256) hmma_dual_kernel(
    const __nv_bfloat16* __restrict__ A,
    const __nv_bfloat16* __restrict__ B1, const float* __restrict__ b1,
    const __nv_bfloat16* __restrict__ B2, const float* __restrict__ b2,
    __nv_bfloat16* __restrict__ outp, int M, int N, int K)
{
    extern __shared__ __align__(16) char smem[];
    uint32_t sb = smem_u32(smem);
    int tid = threadIdx.x, lane = tid & 31, wid = tid >> 5;
    int m0 = blockIdx.y * 128, n0 = blockIdx.x * 64;
    int warp_m = (wid & 1) * 64, warp_n = (wid >> 1) * 16;

    float acc1[4][2][4] = {}, acc2[4][2][4] = {};

    int sub = lane >> 3, lrow = lane & 7;
    uint32_t a_off  = ((warp_m + (sub & 1) * 8 + lrow) * PAD + (sub >> 1) * 8) * 2;
    uint32_t b1_off = DTILE_A + ((warp_n + (sub >> 1) * 8 + lrow) * PAD + (sub & 1) * 8) * 2;
    uint32_t b2_off = DTILE_A + DTILE_B + ((warp_n + (sub >> 1) * 8 + lrow) * PAD + (sub & 1) * 8) * 2;

    const int NCH = K >> 6;
    const int ld4 = K >> 3;
    int lrow4 = tid >> 3, lcol4 = tid & 7;
    const uint4* agl  = (const uint4*)(A  + (size_t)m0 * K) + (size_t)lrow4 * ld4 + lcol4;
    const uint4* bgl1 = (const uint4*)(B1 + (size_t)n0 * K) + (size_t)lrow4 * ld4 + lcol4;
    const uint4* bgl2 = (const uint4*)(B2 + (size_t)n0 * K) + (size_t)lrow4 * ld4 + lcol4;
    uint32_t sdst = sb + lrow4 * (PAD * 2) + lcol4 * 16;
    bool bload = (lrow4 < 64);

    #pragma unroll
    for (int s = 0; s < 2; s++) {
        if (s < NCH) {
            uint32_t d = sdst + s * DSTAGE;
            const uint4* ag = agl + (size_t)s * 8;
            #pragma unroll
            for (int p = 0; p < 4; p++)
                cp16(d + p * 32 * (PAD * 2), ag + (size_t)p * 32 * ld4);
            if (bload) {
                const uint4* bg1 = bgl1 + (size_t)s * 8;
                const uint4* bg2 = bgl2 + (size_t)s * 8;
                cp16(d + DTILE_A,              bg1);
                cp16(d + DTILE_A + 32*(PAD*2), bg1 + (size_t)32 * ld4);
                cp16(d + DTILE_A + DTILE_B,              bg2);
                cp16(d + DTILE_A + DTILE_B + 32*(PAD*2), bg2 + (size_t)32 * ld4);
            }
        }
        CP_COMMIT();
    }

    int stage = 0, lstage = 2;
    for (int c = 0; c < NCH; c++) {
        if (c + 1 < NCH) CP_WAIT1(); else CP_WAIT0();
        __syncthreads();
        if (c + 2 < NCH) {
            uint32_t d = sdst + lstage * DSTAGE;
            const uint4* ag = agl + (size_t)(c + 2) * 8;
            #pragma unroll
            for (int p = 0; p < 4; p++)
                cp16(d + p * 32 * (PAD * 2), ag + (size_t)p * 32 * ld4);
            if (bload) {
                const uint4* bg1 = bgl1 + (size_t)(c + 2) * 8;
                const uint4* bg2 = bgl2 + (size_t)(c + 2) * 8;
                cp16(d + DTILE_A,              bg1);
                cp16(d + DTILE_A + 32*(PAD*2), bg1 + (size_t)32 * ld4);
                cp16(d + DTILE_A + DTILE_B,              bg2);
                cp16(d + DTILE_A + DTILE_B + 32*(PAD*2), bg2 + (size_t)32 * ld4);
            }
            CP_COMMIT();
            if (++lstage == NSTAGE) lstage = 0;
        }
        uint32_t ab  = sb + stage * DSTAGE + a_off;
        uint32_t bb1 = sb + stage * DSTAGE + b1_off;
        uint32_t bb2 = sb + stage * DSTAGE + b2_off;
        #pragma unroll
        for (int ks = 0; ks < 4; ks++) {
            uint32_t af[4][4], bf1[4], bf2[4];
            #pragma unroll
            for (int mt = 0; mt < 4; mt++) ldsm4(af[mt], ab + (mt * 16 * PAD + ks * 16) * 2);
            ldsm4(bf1, bb1 + (ks * 16) * 2);
            ldsm4(bf2, bb2 + (ks * 16) * 2);
            #pragma unroll
            for (int mt = 0; mt < 4; mt++) {
                mma_bf16(acc1[mt][0], af[mt], &bf1[0]);
                mma_bf16(acc1[mt][1], af[mt], &bf1[2]);
                mma_bf16(acc2[mt][0], af[mt], &bf2[0]);
                mma_bf16(acc2[mt][1], af[mt], &bf2[2]);
            }
        }
        if (++stage == NSTAGE) stage = 0;
    }

    int crow = lane >> 2, ccol = (lane & 3) * 2;
    #pragma unroll
    for (int mt = 0; mt < 4; mt++) {
        #pragma unroll
        for (int half = 0; half < 2; half++) {
            int m = m0 + warp_m + mt * 16 + crow + half * 8;
            if (m >= M) continue;
            #pragma unroll
            for (int nt = 0; nt < 2; nt++) {
                int n = n0 + warp_n + nt * 8 + ccol;
                float z0 = acc1[mt][nt][half * 2 + 0] + b1[n];
                float z1 = acc1[mt][nt][half * 2 + 1] + b1[n + 1];
                float g0 = acc2[mt][nt][half * 2 + 0] + b2[n];
                float g1 = acc2[mt][nt][half * 2 + 1] + b2[n + 1];
                float h0 = (z0 / (1.0f + __expf(-z0))) * g0;
                float h1 = (z1 / (1.0f + __expf(-z1))) * g1;
                *(__nv_bfloat162*)(outp + (size_t)m * N + n) = __floats2bfloat162_rn(h0, h1);
            }
        }
    }
}

// ---------------- deformable-attention sampling ----------------
// 2 tokens/block; warp handles (token, head-pair); lane = 16 per head, bf16x2 channels.
__global__ void __launch_bounds__(256) msda_kernel(
    const float* __restrict__ ref,             // (bs, Lq, NL, 2)
    const __nv_bfloat16* __restrict__ value,   // (bs*Lq, 256) bf16
    const float* __restrict__ off,             // (bs*Lq, 256)
    const float* __restrict__ awl,             // (bs*Lq, 128) logits
    __nv_bfloat16* __restrict__ outp)
{
    int tid   = threadIdx.x;
    int wid   = tid >> 5, lane = tid & 31;
    int token = blockIdx.x * 2 + (wid >> 2);
    int h     = ((wid & 3) << 1) + (lane >> 4);
    int ch2   = lane & 15;                     // bf16x2 channel index within head

    const float* aw = awl + (size_t)token * 128 + h * 16;
    const float* of = off + (size_t)token * 256 + h * 32;

    float wgt[16];
    float mx = -1e30f;
    #pragma unroll
    for (int s = 0; s < 16; s++) { wgt[s] = aw[s]; mx = fmaxf(mx, wgt[s]); }
    float sum = 0.f;
    #pragma unroll
    for (int s = 0; s < 16; s++) { wgt[s] = __expf(wgt[s] - mx); sum += wgt[s]; }
    float inv = 1.0f / sum;

    int b = token / LQ;
    const __nv_bfloat162* vb = (const __nv_bfloat162*)value + (size_t)b * LQ * 128 + h * 16 + ch2;

    float ax = 0.f, ay = 0.f;
    #pragma unroll
    for (int l = 0; l < 4; l++) {
        const int H  = c_H[l];
        const int W  = c_W[l];
        const int st = c_st[l];
        float rx = ref[(size_t)token * 8 + l * 2 + 0];
        float ry = ref[(size_t)token * 8 + l * 2 + 1];
        #pragma unroll
        for (int p = 0; p < 4; p++) {
            int s = l * 4 + p;
            float x = fmaf(rx, (float)W, of[s * 2 + 0] - 0.5f);
            float y = fmaf(ry, (float)H, of[s * 2 + 1] - 0.5f);
            float x0f = floorf(x), y0f = floorf(y);
            int   x0  = (int)x0f,  y0  = (int)y0f;
            float lx = x - x0f, ly = y - y0f;
            float ws  = wgt[s] * inv;
            float w00 = (1.f - lx) * (1.f - ly) * ws;
            float w01 = lx * (1.f - ly) * ws;
            float w10 = (1.f - lx) * ly * ws;
            float w11 = lx * ly * ws;
            bool x0v = (x0 >= 0)     && (x0 < W);
            bool x1v = (x0 + 1 >= 0) && (x0 + 1 < W);
            if (y0 >= 0 && y0 < H) {
                long long base = (long long)(st + y0 * W) * 128;
                if (x0v) { float2 f = __bfloat1622float2(vb[base + (long long)x0 * 128]);
                           ax += w00 * f.x; ay += w00 * f.y; }
                if (x1v) { float2 f = __bfloat1622float2(vb[base + (long long)(x0 + 1) * 128]);
                           ax += w01 * f.x; ay += w01 * f.y; }
            }
            int y1 = y0 + 1;
            if (y1 >= 0 && y1 < H) {
                long long base = (long long)(st + y1 * W) * 128;
                if (x0v) { float2 f = __bfloat1622float2(vb[base + (long long)x0 * 128]);
                           ax += w10 * f.x; ay += w10 * f.y; }
                if (x1v) { float2 f = __bfloat1622float2(vb[base + (long long)(x0 + 1) * 128]);
                           ax += w11 * f.x; ay += w11 * f.y; }
            }
        }
    }
    *(__nv_bfloat162*)(outp + (size_t)token * 256 + h * 32 + ch2 * 2) = __floats2bfloat162_rn(ax, ay);
}

// ---------------- host launch ----------------
template <typename T>
static T* symaddr(const void* sym) {
    void* p = nullptr;
    cudaGetSymbolAddress(&p, sym);
    return (T*)p;
}

extern "C" void kernel_launch(void* const* d_in, const int* in_sizes, int n_in,
                              void* d_out, int out_size) {
    (void)in_sizes; (void)n_in; (void)out_size;
    const float* query = (const float*)d_in[0];
    const float* qpos  = (const float*)d_in[1];
    const float* ref   = (const float*)d_in[2];
    const float* nw1   = (const float*)d_in[5];
    const float* Wv    = (const float*)d_in[6];
    const float* bv    = (const float*)d_in[7];
    const float* Woff  = (const float*)d_in[8];
    const float* boff  = (const float*)d_in[9];
    const float* Waw   = (const float*)d_in[10];
    const float* baw   = (const float*)d_in[11];
    const float* Wo    = (const float*)d_in[12];
    const float* bo    = (const float*)d_in[13];
    const float* lsa   = (const float*)d_in[14];
    const float* nw2   = (const float*)d_in[15];
    const float* W1    = (const float*)d_in[16];
    const float* b1    = (const float*)d_in[17];
    const float* W2    = (const float*)d_in[18];
    const float* b2    = (const float*)d_in[19];
    const float* W3    = (const float*)d_in[20];
    const float* b3    = (const float*)d_in[21];
    const float* lsf   = (const float*)d_in[22];
    float* out = (float*)d_out;

    __nv_bfloat16* nb    = symaddr<__nv_bfloat16>(g_nb);
    __nv_bfloat16* qb    = symaddr<__nv_bfloat16>(g_qb);
    __nv_bfloat16* valb  = symaddr<__nv_bfloat16>(g_valueb);
    float*         poff  = symaddr<float>(g_off);
    float*         pawl  = symaddr<float>(g_awl);
    __nv_bfloat16* attnb = symaddr<__nv_bfloat16>(g_attnb);
    float*         px    = symaddr<float>(g_x);
    __nv_bfloat16* n2b   = symaddr<__nv_bfloat16>(g_n2b);
    __nv_bfloat16* hb    = symaddr<__nv_bfloat16>(g_hb);
    __nv_bfloat16* wb    = symaddr<__nv_bfloat16>(g_wb);

    const int GSM = NSTAGE * STAGE_BYTES;   // 110592
    const int DSM = NSTAGE * DSTAGE;        // 110592
    cudaFuncSetAttribute(hmma_gemm_kernel, cudaFuncAttributeMaxDynamicSharedMemorySize, GSM);
    cudaFuncSetAttribute(hmma_dual_kernel, cudaFuncAttributeMaxDynamicSharedMemorySize, DSM);

    // 0. weights -> bf16
    WSrc ws; ws.s[0] = Wv; ws.s[1] = Woff; ws.s[2] = Waw; ws.s[3] = Wo;
    ws.s[4] = W1; ws.s[5] = W2; ws.s[6] = W3;
    wconv_kernel<<<dim3(256, 7), 256>>>(ws);

    // 1. rmsnorm -> normed bf16, q = normed+pos bf16
    rmsnorm_kernel<<<(MTOK + 7) / 8, 256>>>(query, nw1, nb, qpos, qb);
    // 2. value = normed @ Wv^T + bv  (bf16 out)
    hmma_gemm_kernel<<<dim3(2, MT128), 256, GSM>>>(nb, wb + WOFF_WV, bv, nullptr,
        nullptr, nullptr, valb, MTOK, 256, 256, 256, nullptr, nullptr);
    // 3. fused offsets+logits: q @ [Woff;Waw]^T, split outputs
    hmma_gemm_kernel<<<dim3(3, MT128), 256, GSM>>>(qb, wb + WOFF_WOFF, boff, baw,
        poff, pawl, nullptr, MTOK, 384, 256, 256, nullptr, nullptr);
    // 4. deformable sampling -> attn bf16
    msda_kernel<<<MTOK / 2, 256>>>(ref, valb, poff, pawl, attnb);
    // 5. x = query + ls_attn * (attn @ Wo^T + bo)
    hmma_gemm_kernel<<<dim3(2, MT128), 256, GSM>>>(attnb, wb + WOFF_WO, bo, nullptr,
        px, nullptr, nullptr, MTOK, 256, 256, 256, query, lsa);
    // 6. n2 = rmsnorm(x) bf16
    rmsnorm_kernel<<<(MTOK + 7) / 8, 256>>>(px, nw2, n2b, nullptr, nullptr);
    // 7. h = silu(n2@W1^T+b1)*(n2@W2^T+b2) bf16
    hmma_dual_kernel<<<dim3(16, MT128), 256, DSM>>>(n2b, wb + WOFF_W1, b1, wb + WOFF_W2, b2, hb, MTOK, DFFN, 256);
    // 8. out = x + ls_ffn * (h @ W3^T + b3)
    hmma_gemm_kernel<<<dim3(2, MT128), 256, GSM>>>(hb, wb + WOFF_W3, b3, nullptr,
        out, nullptr, nullptr, MTOK, 256, 256, 1024, px, lsf);
}